// round 17
// baseline (speedup 1.0000x reference)
#include <cuda_runtime.h>
#include <cuda_bf16.h>
#include <math.h>
#include <stdint.h>

#define B_  64
#define E_  512
#define H_  512
#define V_  32000
#define T_  32
#define G4  2048   // 4*H

typedef unsigned long long ull;

// ---------------- persistent device state ----------------
__device__ __align__(16) float g_c[B_ * H_];        // cell state
__device__ __align__(16) float g_gates[4][B_ * G4]; // planes: ih-k0, ih-k1, hh-k0, hh-k1
__device__ ull g_amax[2][B_];                       // packed argmax accumulators
// bf16 2-term splits (gates path)
__device__ __align__(16) __nv_bfloat16 g_Ib1[2048 * 512];
__device__ __align__(16) __nv_bfloat16 g_Ib2[2048 * 512];
__device__ __align__(16) __nv_bfloat16 g_Hb1[2048 * 512];
__device__ __align__(16) __nv_bfloat16 g_Hb2[2048 * 512];
__device__ __align__(16) __nv_bfloat16 g_hb[2][B_ * 512];   // h(t) bf16 splits (gates)
// int8 dual-plane quantization (logits path)
__device__ __align__(16) signed char g_W8h[(size_t)V_ * 512];
__device__ __align__(16) signed char g_W8l[(size_t)V_ * 512];
__device__ float g_sW[V_];
__device__ __align__(16) signed char g_h8h[B_ * 512];
__device__ __align__(16) signed char g_h8l[B_ * 512];
__device__ float g_sh[B_];

__device__ __forceinline__ unsigned fkey(float f) {
    unsigned u = __float_as_uint(f);
    return (u & 0x80000000u) ? ~u : (u | 0x80000000u);
}
__device__ __forceinline__ uint32_t smem_u32(const void* p) {
    uint32_t a;
    asm("{ .reg .u64 t; cvta.to.shared.u64 t, %1; cvt.u32.u64 %0, t; }" : "=r"(a) : "l"(p));
    return a;
}
__device__ __forceinline__ void ldsm4(uint32_t* r, uint32_t addr) {
    asm volatile("ldmatrix.sync.aligned.m8n8.x4.shared.b16 {%0,%1,%2,%3}, [%4];"
        : "=r"(r[0]), "=r"(r[1]), "=r"(r[2]), "=r"(r[3]) : "r"(addr));
}
__device__ __forceinline__ void mma16816(float* d, const uint32_t* a, uint32_t b0, uint32_t b1) {
    asm volatile("mma.sync.aligned.m16n8k16.row.col.f32.bf16.bf16.f32 "
        "{%0,%1,%2,%3}, {%4,%5,%6,%7}, {%8,%9}, {%0,%1,%2,%3};"
        : "+f"(d[0]), "+f"(d[1]), "+f"(d[2]), "+f"(d[3])
        : "r"(a[0]), "r"(a[1]), "r"(a[2]), "r"(a[3]), "r"(b0), "r"(b1));
}
__device__ __forceinline__ void imma(int* d, const uint32_t* a, uint32_t b0, uint32_t b1) {
    asm volatile("mma.sync.aligned.m16n8k32.row.col.s32.s8.s8.s32 "
        "{%0,%1,%2,%3}, {%4,%5,%6,%7}, {%8,%9}, {%0,%1,%2,%3};"
        : "+r"(d[0]), "+r"(d[1]), "+r"(d[2]), "+r"(d[3])
        : "r"(a[0]), "r"(a[1]), "r"(a[2]), "r"(a[3]), "r"(b0), "r"(b1));
}
__device__ __forceinline__ void cpasync16(uint32_t dst, const void* src) {
    asm volatile("cp.async.cg.shared.global [%0], [%1], 16;" :: "r"(dst), "l"(src));
}
#define SW128(o) ((o) ^ (((o) >> 3) & 0x70))

// k_prep smem: W1 16K | W2 16K | H1 8K | H2 8K, x2 buffers
// k_big  smem: Whi 16K | Wlo 16K | hhi 8K | hlo 8K, x2 buffers (same geometry)
#define DSM_STRIDE 49152
#define DSM_W1 0
#define DSM_W2 16384
#define DSM_H1 32768
#define DSM_H2 40960
#define DSM_TOT (2 * DSM_STRIDE)

// =========================================================
// k_splitall: bf16 splits for gates path (W_ih, W_hh, features->g_hb).
// grid 8320 x 256.
// =========================================================
__global__ __launch_bounds__(256) void k_splitall(
    const float* __restrict__ W_ih, const float* __restrict__ W_hh,
    const float* __restrict__ features)
{
    const int bid = blockIdx.x;
    const int tid = threadIdx.x;
    if (bid < 4096) {
        int i = bid * 256 + tid;
        float w = W_ih[i];
        __nv_bfloat16 h1 = __float2bfloat16(w);
        g_Ib1[i] = h1;
        g_Ib2[i] = __float2bfloat16(w - __bfloat162float(h1));
    } else if (bid < 8192) {
        int i = (bid - 4096) * 256 + tid;
        float w = W_hh[i];
        __nv_bfloat16 h1 = __float2bfloat16(w);
        g_Hb1[i] = h1;
        g_Hb2[i] = __float2bfloat16(w - __bfloat162float(h1));
    } else {
        int i = (bid - 8192) * 256 + tid;
        float f = features[i];
        __nv_bfloat16 h1 = __float2bfloat16(f);
        g_hb[0][i] = h1;
        g_hb[1][i] = __float2bfloat16(f - __bfloat162float(h1));
    }
}

// =========================================================
// k_wq: per-row int16 quantization of lin_W into s8 hi/lo planes.
// grid 32000 x 128 (4 elems/thread).
// =========================================================
__global__ __launch_bounds__(128) void k_wq(const float* __restrict__ lin_W)
{
    __shared__ float red[4];
    const int v = blockIdx.x, tid = threadIdx.x;
    const float* src = lin_W + (size_t)v * 512 + tid * 4;
    float4 w = *(const float4*)src;
    float m = fmaxf(fmaxf(fabsf(w.x), fabsf(w.y)), fmaxf(fabsf(w.z), fabsf(w.w)));
    #pragma unroll
    for (int s = 16; s >= 1; s >>= 1) m = fmaxf(m, __shfl_xor_sync(0xFFFFFFFFu, m, s));
    if ((tid & 31) == 0) red[tid >> 5] = m;
    __syncthreads();
    if (tid == 0) {
        float mm = fmaxf(fmaxf(red[0], red[1]), fmaxf(red[2], red[3]));
        red[0] = mm / 32511.0f + 1e-30f;
        g_sW[v] = red[0];
    }
    __syncthreads();
    const float inv = 1.0f / red[0];
    char hi[4], lo[4];
    float wv[4] = {w.x, w.y, w.z, w.w};
    #pragma unroll
    for (int i = 0; i < 4; i++) {
        int q = __float2int_rn(wv[i] * inv);
        q = max(-32512, min(32511, q));
        int l8 = (int)(signed char)(q & 0xFF);
        hi[i] = (char)((q - l8) >> 8);
        lo[i] = (char)l8;
    }
    *(char4*)(g_W8h + (size_t)v * 512 + tid * 4) = *(char4*)hi;
    *(char4*)(g_W8l + (size_t)v * 512 + tid * 4) = *(char4*)lo;
}

// =========================================================
// k_prep: gate partials via HMMA bf16 3-pass (unchanged math).
// grid 64: wsel = bid>>5 (0: W_ih@embed[tok], 1: W_hh@h), sub = bid&31.
// =========================================================
__global__ __launch_bounds__(256) void k_prep(
    int t, const void* __restrict__ captions, const float* __restrict__ embed)
{
    extern __shared__ char dsm[];
    __shared__ int stok[B_];
    const uint32_t sb = smem_u32(dsm);
    const int tid = threadIdx.x;
    const int bid = blockIdx.x;
    const int wid = tid >> 5, lid = tid & 31;

    const int wsel  = bid >> 5;
    const int sub   = bid & 31;
    const int rb    = (sub >> 1) * 128;
    const int kbase = (sub & 1) * 256;

    if (t == 0 && bid == 0 && tid < 128)
        g_amax[tid >> 6][tid & 63] = 0ull;

    if (wsel == 0 && tid < B_) {
        int tok;
        if (t == 0) {
            const int* ci = (const int*)captions;
            bool is64 = true;
            #pragma unroll
            for (int i = 1; i < 32; i += 2) if (ci[i]) is64 = false;
            tok = is64 ? (int)((const long long*)captions)[tid] : ci[tid];
        } else {
            ull pk = g_amax[(t + 1) & 1][tid];
            tok = (int)(0x7FFFFFFFu - (unsigned)(pk & 0xFFFFFFFFull));
        }
        stok[tid] = tok;
    }
    __syncthreads();

    const __nv_bfloat16* A1 = wsel ? g_Hb1 : g_Ib1;
    const __nv_bfloat16* A2 = wsel ? g_Hb2 : g_Ib2;

    auto stage = [&](int buf, int c) {
        const int k0 = kbase + c * 64;
        uint32_t base = sb + buf * DSM_STRIDE;
        #pragma unroll
        for (int q = 0; q < 4; q++) {
            int idx = tid + q * 256;
            int r = idx >> 3, uu = idx & 7;
            uint32_t dst = SW128((uint32_t)(r * 128 + uu * 16));
            size_t so = (size_t)(rb + r) * 512 + k0 + uu * 8;
            cpasync16(base + DSM_W1 + dst, A1 + so);
            cpasync16(base + DSM_W2 + dst, A2 + so);
        }
        if (wsel) {
            #pragma unroll
            for (int q = 0; q < 2; q++) {
                int idx = tid + q * 256;
                int b = idx >> 3, uu = idx & 7;
                uint32_t dst = SW128((uint32_t)(b * 128 + uu * 16));
                size_t so = (size_t)b * 512 + k0 + uu * 8;
                cpasync16(base + DSM_H1 + dst, g_hb[0] + so);
                cpasync16(base + DSM_H2 + dst, g_hb[1] + so);
            }
            asm volatile("cp.async.commit_group;" ::: "memory");
        } else {
            asm volatile("cp.async.commit_group;" ::: "memory");
            #pragma unroll
            for (int q = 0; q < 4; q++) {
                int idx = tid + q * 256;
                int b = idx >> 4, kk = (idx & 15) * 4;
                float4 x = *(const float4*)(embed + (size_t)stok[b] * E_ + k0 + kk);
                __nv_bfloat16 hx = __float2bfloat16(x.x), hy = __float2bfloat16(x.y);
                __nv_bfloat16 hz = __float2bfloat16(x.z), hw = __float2bfloat16(x.w);
                __nv_bfloat162 hi0; hi0.x = hx; hi0.y = hy;
                __nv_bfloat162 hi1; hi1.x = hz; hi1.y = hw;
                __nv_bfloat162 lo0, lo1;
                lo0.x = __float2bfloat16(x.x - __bfloat162float(hx));
                lo0.y = __float2bfloat16(x.y - __bfloat162float(hy));
                lo1.x = __float2bfloat16(x.z - __bfloat162float(hz));
                lo1.y = __float2bfloat16(x.w - __bfloat162float(hw));
                uint32_t dst = SW128((uint32_t)(b * 128 + kk * 2));
                ull hp, lp;
                memcpy(&hp, &hi0, 4); memcpy(((char*)&hp) + 4, &hi1, 4);
                memcpy(&lp, &lo0, 4); memcpy(((char*)&lp) + 4, &lo1, 4);
                *(ull*)(dsm + buf * DSM_STRIDE + DSM_H1 + dst) = hp;
                *(ull*)(dsm + buf * DSM_STRIDE + DSM_H2 + dst) = lp;
            }
        }
    };

    const int sel = lid >> 3, row = lid & 7;
    const int aV  = 16 * wid + ((sel & 1) << 3) + row;
    const int aKo = (sel >> 1) << 3;
    const int bB  = ((sel >> 1) << 3) + row;
    const int bKo = (sel & 1) << 3;

    float acc[8][4] = {};
    stage(0, 0);
    for (int c = 0; c < 4; c++) {
        if (c < 3) {
            stage((c + 1) & 1, c + 1);
            asm volatile("cp.async.wait_group 1;" ::: "memory");
        } else {
            asm volatile("cp.async.wait_group 0;" ::: "memory");
        }
        __syncthreads();
        const uint32_t base = sb + (c & 1) * DSM_STRIDE;
        #pragma unroll
        for (int kk = 0; kk < 64; kk += 16) {
            uint32_t a1[4], a2[4];
            uint32_t aoff = SW128((uint32_t)(aV * 128 + (kk + aKo) * 2));
            ldsm4(a1, base + DSM_W1 + aoff);
            ldsm4(a2, base + DSM_W2 + aoff);
            #pragma unroll
            for (int jp = 0; jp < 4; jp++) {
                uint32_t b1[4], b2[4];
                uint32_t boff = SW128((uint32_t)((16 * jp + bB) * 128 + (kk + bKo) * 2));
                ldsm4(b1, base + DSM_H1 + boff);
                ldsm4(b2, base + DSM_H2 + boff);
                mma16816(acc[2 * jp],     a1, b1[0], b1[1]);
                mma16816(acc[2 * jp + 1], a1, b1[2], b1[3]);
                mma16816(acc[2 * jp],     a1, b2[0], b2[1]);
                mma16816(acc[2 * jp + 1], a1, b2[2], b2[3]);
                mma16816(acc[2 * jp],     a2, b1[0], b1[1]);
                mma16816(acc[2 * jp + 1], a2, b1[2], b1[3]);
            }
        }
        __syncthreads();
    }

    float* gp = g_gates[wsel * 2 + (sub & 1)];
    const int qrow = lid >> 2, qcol = lid & 3;
    const int r0 = rb + 16 * wid + qrow;
    const int r1 = r0 + 8;
    #pragma unroll
    for (int j = 0; j < 8; j++) {
        int blo = 8 * j + 2 * qcol, bhi = blo + 1;
        gp[(size_t)blo * G4 + r0] = acc[j][0];
        gp[(size_t)bhi * G4 + r0] = acc[j][1];
        gp[(size_t)blo * G4 + r1] = acc[j][2];
        gp[(size_t)bhi * G4 + r1] = acc[j][3];
    }
}

// =========================================================
// k_update: LSTM nonlinearity; writes c, bf16 h splits, AND int16(s8x2) h quant.
// grid 64 x 512 (one block per batch row).
// =========================================================
__global__ __launch_bounds__(512) void k_update(
    int t, const float* __restrict__ features,
    const float* __restrict__ b_ih, const float* __restrict__ b_hh)
{
    __shared__ float red[16];
    const int b = blockIdx.x, j = threadIdx.x;
    const int base = b * G4;

    float z[4];
    #pragma unroll
    for (int g = 0; g < 4; g++) {
        int o = base + j + g * 512;
        z[g] = b_ih[j + g * 512] + b_hh[j + g * 512]
             + g_gates[0][o] + g_gates[1][o] + g_gates[2][o] + g_gates[3][o];
    }
    float i_ = 1.0f / (1.0f + expf(-z[0]));
    float f_ = 1.0f / (1.0f + expf(-z[1]));
    float gg = tanhf(z[2]);
    float o_ = 1.0f / (1.0f + expf(-z[3]));

    float c_old = (t == 0) ? features[b * H_ + j] : g_c[b * H_ + j];
    float c_new = f_ * c_old + i_ * gg;
    float h_new = o_ * tanhf(c_new);

    g_c[b * H_ + j] = c_new;
    __nv_bfloat16 h1 = __float2bfloat16(h_new);
    g_hb[0][b * 512 + j] = h1;
    g_hb[1][b * 512 + j] = __float2bfloat16(h_new - __bfloat162float(h1));

    // per-row max for int16 quantization
    float a = fabsf(h_new);
    #pragma unroll
    for (int s = 16; s >= 1; s >>= 1) a = fmaxf(a, __shfl_xor_sync(0xFFFFFFFFu, a, s));
    if ((j & 31) == 0) red[j >> 5] = a;
    __syncthreads();
    if (j == 0) {
        float mm = red[0];
        #pragma unroll
        for (int w = 1; w < 16; w++) mm = fmaxf(mm, red[w]);
        float s = mm / 32511.0f + 1e-30f;
        red[0] = s;
        g_sh[b] = s;
    }
    __syncthreads();
    const float inv = 1.0f / red[0];
    int q = __float2int_rn(h_new * inv);
    q = max(-32512, min(32511, q));
    int l8 = (int)(signed char)(q & 0xFF);
    g_h8h[b * 512 + j] = (signed char)((q - l8) >> 8);
    g_h8l[b * 512 + j] = (signed char)l8;
}

// =========================================================
// k_big: logits via IMMA s8 3-pass (65536*HH + 256*(HL+LH); LL dropped).
// grid 250 x 256. Block: 128v x 64b x 512k (4 chunks of 128k s8).
// Warp w: wv = w&3 (32-v group), wb = w>>2 (32-b half). Tile 32v x 32b.
// =========================================================
__device__ __forceinline__ void stage_q(uint32_t sb, int buf, int vb, int k0, int tid)
{
    uint32_t base = sb + buf * DSM_STRIDE;
    #pragma unroll
    for (int q = 0; q < 4; q++) {
        int idx = tid + q * 256;          // 0..1023: 128v x 8 segs
        int v = idx >> 3, uu = idx & 7;
        uint32_t dst = SW128((uint32_t)(v * 128 + uu * 16));
        size_t so = (size_t)(vb + v) * 512 + k0 + uu * 16;
        cpasync16(base + DSM_W1 + dst, g_W8h + so);
        cpasync16(base + DSM_W2 + dst, g_W8l + so);
    }
    #pragma unroll
    for (int q = 0; q < 2; q++) {
        int idx = tid + q * 256;          // 0..511: 64b x 8 segs
        int b = idx >> 3, uu = idx & 7;
        uint32_t dst = SW128((uint32_t)(b * 128 + uu * 16));
        size_t so = (size_t)b * 512 + k0 + uu * 16;
        cpasync16(base + DSM_H1 + dst, g_h8h + so);
        cpasync16(base + DSM_H2 + dst, g_h8l + so);
    }
    asm volatile("cp.async.commit_group;" ::: "memory");
}

__global__ __launch_bounds__(256, 2) void k_big(
    int t, const float* __restrict__ lin_b, float* __restrict__ out)
{
    extern __shared__ char dsm[];
    __shared__ ull s_amax[64];
    const uint32_t sb = smem_u32(dsm);
    const int tid = threadIdx.x;
    const int bid = blockIdx.x;
    const int wid = tid >> 5, lid = tid & 31;
    const int vb = bid * 128;

    if (tid < 64) s_amax[tid] = 0ull;
    if (bid == 0 && tid < 64) g_amax[(t + 1) & 1][tid] = 0ull;

    const int wv = wid & 3;         // v-group (32 rows)
    const int wb = wid >> 2;        // b-half (32 cols)
    const int sel = lid >> 3, row = lid & 7;
    const int aRow = ((sel & 1) << 3) + row;
    const int aByt = (sel >> 1) << 4;
    const int bRow = ((sel >> 1) << 3) + row;
    const int bByt = (sel & 1) << 4;

    int   HH[2][4][4] = {};         // exact int accumulation (|HH|<=8.26e6 < 2^23)
    float fac[2][4][4] = {};        // 256*(HL+LH) folded per kk

    stage_q(sb, 0, vb, 0, tid);
    for (int c = 0; c < 4; c++) {
        if (c < 3) {
            stage_q(sb, (c + 1) & 1, vb, (c + 1) * 128, tid);
            asm volatile("cp.async.wait_group 1;" ::: "memory");
        } else {
            asm volatile("cp.async.wait_group 0;" ::: "memory");
        }
        __syncthreads();
        const uint32_t base = sb + (c & 1) * DSM_STRIDE;

        #pragma unroll
        for (int kk = 0; kk < 4; kk++) {
            uint32_t Ah[2][4], Al[2][4], Bh[2][4], Bl[2][4];
            #pragma unroll
            for (int mt = 0; mt < 2; mt++) {
                uint32_t aoff = SW128((uint32_t)((32 * wv + 16 * mt + aRow) * 128 + kk * 32 + aByt));
                ldsm4(Ah[mt], base + DSM_W1 + aoff);
                ldsm4(Al[mt], base + DSM_W2 + aoff);
            }
            #pragma unroll
            for (int jh = 0; jh < 2; jh++) {
                uint32_t boff = SW128((uint32_t)((32 * wb + 16 * jh + bRow) * 128 + kk * 32 + bByt));
                ldsm4(Bh[jh], base + DSM_H1 + boff);
                ldsm4(Bl[jh], base + DSM_H2 + boff);
            }
            #pragma unroll
            for (int mt = 0; mt < 2; mt++)
                #pragma unroll
                for (int jn = 0; jn < 4; jn++) {
                    const int jh = jn >> 1, jo = (jn & 1) * 2;
                    imma(HH[mt][jn], Ah[mt], Bh[jh][jo], Bh[jh][jo + 1]);
                    int d[4] = {0, 0, 0, 0};
                    imma(d, Ah[mt], Bl[jh][jo], Bl[jh][jo + 1]);
                    imma(d, Al[mt], Bh[jh][jo], Bh[jh][jo + 1]);
                    #pragma unroll
                    for (int i = 0; i < 4; i++)
                        fac[mt][jn][i] = fmaf(256.0f, (float)d[i], fac[mt][jn][i]);
                }
        }
        __syncthreads();
    }

    // epilogue: combine, scale, bias, store, argmax
    const int qrow = lid >> 2, qcol = lid & 3;
    #pragma unroll
    for (int jn = 0; jn < 4; jn++) {
        const int blo = 32 * wb + 8 * jn + 2 * qcol, bhi = blo + 1;
        const float shl = g_sh[blo], shh = g_sh[bhi];
        ull klo = 0ull, khi = 0ull;
        #pragma unroll
        for (int mt = 0; mt < 2; mt++) {
            const int v0 = vb + 32 * wv + 16 * mt + qrow;
            const int v1 = v0 + 8;
            const float sv0 = g_sW[v0], sv1 = g_sW[v1];
            const float bi0 = lin_b[v0], bi1 = lin_b[v1];
            float t0 = fmaf(65536.0f, (float)HH[mt][jn][0], fac[mt][jn][0]);
            float t1 = fmaf(65536.0f, (float)HH[mt][jn][1], fac[mt][jn][1]);
            float t2 = fmaf(65536.0f, (float)HH[mt][jn][2], fac[mt][jn][2]);
            float t3 = fmaf(65536.0f, (float)HH[mt][jn][3], fac[mt][jn][3]);
            float c0 = t0 * (sv0 * shl) + bi0;
            float c1 = t1 * (sv0 * shh) + bi0;
            float c2 = t2 * (sv1 * shl) + bi1;
            float c3 = t3 * (sv1 * shh) + bi1;
            out[((size_t)blo * T_ + t) * V_ + v0] = c0;
            out[((size_t)bhi * T_ + t) * V_ + v0] = c1;
            out[((size_t)blo * T_ + t) * V_ + v1] = c2;
            out[((size_t)bhi * T_ + t) * V_ + v1] = c3;
            ull p;
            p = ((ull)fkey(c0) << 32) | (ull)(0x7FFFFFFFu - (unsigned)v0); if (p > klo) klo = p;
            p = ((ull)fkey(c2) << 32) | (ull)(0x7FFFFFFFu - (unsigned)v1); if (p > klo) klo = p;
            p = ((ull)fkey(c1) << 32) | (ull)(0x7FFFFFFFu - (unsigned)v0); if (p > khi) khi = p;
            p = ((ull)fkey(c3) << 32) | (ull)(0x7FFFFFFFu - (unsigned)v1); if (p > khi) khi = p;
        }
        #pragma unroll
        for (int s = 4; s < 32; s <<= 1) {
            ull o1 = __shfl_xor_sync(0xFFFFFFFFu, klo, s); if (o1 > klo) klo = o1;
            ull o2 = __shfl_xor_sync(0xFFFFFFFFu, khi, s); if (o2 > khi) khi = o2;
        }
        if (lid < 4) {
            atomicMax(&s_amax[blo], klo);
            atomicMax(&s_amax[bhi], khi);
        }
    }
    __syncthreads();
    if (tid < 64) atomicMax(&g_amax[t & 1][tid], s_amax[tid]);
}

// =========================================================
extern "C" void kernel_launch(void* const* d_in, const int* in_sizes, int n_in,
                              void* d_out, int out_size)
{
    const float* features = (const float*)d_in[0];
    const void*  captions = d_in[1];
    int off = (in_sizes[2] == V_ * E_) ? 0 : 1;   // 'lengths' may be materialized
    const float* embed = (const float*)d_in[2 + off];
    const float* W_ih  = (const float*)d_in[3 + off];
    const float* W_hh  = (const float*)d_in[4 + off];
    const float* b_ih  = (const float*)d_in[5 + off];
    const float* b_hh  = (const float*)d_in[6 + off];
    const float* lin_W = (const float*)d_in[7 + off];
    const float* lin_b = (const float*)d_in[8 + off];
    float* out = (float*)d_out;
    (void)n_in; (void)out_size;

    cudaFuncSetAttribute(k_big,  cudaFuncAttributeMaxDynamicSharedMemorySize, DSM_TOT);
    cudaFuncSetAttribute(k_prep, cudaFuncAttributeMaxDynamicSharedMemorySize, DSM_TOT);

    // one-time prologue: bf16 splits (gates) + int8 dual-plane quant (logits)
    k_splitall<<<8320, 256>>>(W_ih, W_hh, features);
    k_wq<<<V_, 128>>>(lin_W);

    for (int t = 0; t < T_; t++) {
        k_prep<<<64, 256, DSM_TOT>>>(t, captions, embed);
        k_update<<<64, 512>>>(t, features, b_ih, b_hh);
        k_big<<<250, 256, DSM_TOT>>>(t, lin_b, out);
    }
}